// round 3
// baseline (speedup 1.0000x reference)
#include <cuda_runtime.h>
#include <math.h>

#define N_NODES 8192
#define N_EDGE  512
#define DIM     1024
#define HID     1024

// output float offsets: (edges, H, dots)
#define E_OFF 0
#define H_OFF (N_EDGE * DIM)                 // 524288
#define DOTS_OFF (H_OFF + N_NODES * N_EDGE)  // 4718592

// ---------------- scratch (static device memory; no allocations) ----------------
__device__ float g_x  [N_NODES * DIM];
__device__ float g_k  [N_NODES * DIM];
__device__ float g_v  [N_NODES * DIM];
__device__ float g_q2 [N_NODES * DIM];
__device__ float g_e0 [N_EDGE * DIM];
__device__ float g_q  [N_EDGE * DIM];
__device__ float g_cat[N_EDGE * 2 * DIM];
__device__ float g_h1 [N_EDGE * HID];
__device__ float g_k2 [N_EDGE * DIM];
__device__ float g_dv [N_NODES * N_EDGE];

// ---------------- reduction helpers ----------------
__device__ __forceinline__ float blockReduceSum(float val, float* shm) {
    int lane = threadIdx.x & 31, wid = threadIdx.x >> 5;
    #pragma unroll
    for (int o = 16; o > 0; o >>= 1) val += __shfl_down_sync(0xffffffffu, val, o);
    if (lane == 0) shm[wid] = val;
    __syncthreads();
    int nw = (blockDim.x + 31) >> 5;
    val = (threadIdx.x < nw) ? shm[threadIdx.x] : 0.f;
    if (wid == 0) {
        #pragma unroll
        for (int o = 16; o > 0; o >>= 1) val += __shfl_down_sync(0xffffffffu, val, o);
        if (lane == 0) shm[0] = val;
    }
    __syncthreads();
    float r = shm[0];
    __syncthreads();
    return r;
}

__device__ __forceinline__ float blockReduceMax(float val, float* shm) {
    int lane = threadIdx.x & 31, wid = threadIdx.x >> 5;
    #pragma unroll
    for (int o = 16; o > 0; o >>= 1) val = fmaxf(val, __shfl_down_sync(0xffffffffu, val, o));
    if (lane == 0) shm[wid] = val;
    __syncthreads();
    int nw = (blockDim.x + 31) >> 5;
    val = (threadIdx.x < nw) ? shm[threadIdx.x] : -INFINITY;
    if (wid == 0) {
        #pragma unroll
        for (int o = 16; o > 0; o >>= 1) val = fmaxf(val, __shfl_down_sync(0xffffffffu, val, o));
        if (lane == 0) shm[0] = val;
    }
    __syncthreads();
    float r = shm[0];
    __syncthreads();
    return r;
}

__device__ __forceinline__ unsigned blockReduceSumU(unsigned val, unsigned* shm) {
    int lane = threadIdx.x & 31, wid = threadIdx.x >> 5;
    #pragma unroll
    for (int o = 16; o > 0; o >>= 1) val += __shfl_down_sync(0xffffffffu, val, o);
    if (lane == 0) shm[wid] = val;
    __syncthreads();
    int nw = (blockDim.x + 31) >> 5;
    val = (threadIdx.x < nw) ? shm[threadIdx.x] : 0u;
    if (wid == 0) {
        #pragma unroll
        for (int o = 16; o > 0; o >>= 1) val += __shfl_down_sync(0xffffffffu, val, o);
        if (lane == 0) shm[0] = val;
    }
    __syncthreads();
    unsigned r = shm[0];
    __syncthreads();
    return r;
}

// order-preserving float -> uint key
__device__ __forceinline__ unsigned fkey(float f) {
    unsigned u = __float_as_uint(f);
    return u ^ (((int)u >> 31) | 0x80000000u);
}

// ---------------- layernorm: out = (x-mean)/sqrt(var+1e-5)*g + b ----------------
__global__ __launch_bounds__(256) void ln_kernel(
    const float* __restrict__ in, const float* __restrict__ g, const float* __restrict__ b,
    float* __restrict__ out, int ncols)
{
    __shared__ float shm[32];
    int row = blockIdx.x;
    const float* x = in + (size_t)row * ncols;
    float* y = out + (size_t)row * ncols;
    float s = 0.f, s2 = 0.f;
    for (int i = threadIdx.x; i < ncols; i += blockDim.x) { float v = x[i]; s += v; s2 += v * v; }
    float S  = blockReduceSum(s,  shm);
    float S2 = blockReduceSum(s2, shm);
    float mean = S / ncols;
    float var  = S2 / ncols - mean * mean;
    float inv  = rsqrtf(var + 1e-5f);
    for (int i = threadIdx.x; i < ncols; i += blockDim.x)
        y[i] = (x[i] - mean) * inv * g[i] + b[i];
}

// ---------------- edge sample + layernorm ----------------
__global__ __launch_bounds__(256) void edge_ln_kernel(
    const float* __restrict__ noise, const float* __restrict__ mu, const float* __restrict__ ls,
    const float* __restrict__ g, const float* __restrict__ b, float* __restrict__ out)
{
    __shared__ float shm[32];
    int row = blockIdx.x;
    const float* nz = noise + (size_t)row * DIM;
    float* y = out + (size_t)row * DIM;
    float s = 0.f, s2 = 0.f;
    for (int i = threadIdx.x; i < DIM; i += blockDim.x) {
        float v = mu[i] + expf(ls[i]) * nz[i];
        s += v; s2 += v * v;
    }
    float S  = blockReduceSum(s,  shm);
    float S2 = blockReduceSum(s2, shm);
    float mean = S / DIM;
    float var  = S2 / DIM - mean * mean;
    float inv  = rsqrtf(var + 1e-5f);
    for (int i = threadIdx.x; i < DIM; i += blockDim.x) {
        float v = mu[i] + expf(ls[i]) * nz[i];
        y[i] = (v - mean) * inv * g[i] + b[i];
    }
}

// ---------------- SGEMM NN: C[M,Nc] = act(A[M,K] @ B[K,Nc] + bias) ----------------
// BM=BN=64, BK=16, 256 threads, 4x4 microtile with stride-16 mapping (conflict free)
template <int RELU>
__global__ __launch_bounds__(256) void gemm_nn(
    const float* __restrict__ A, const float* __restrict__ B, const float* __restrict__ bias,
    float* __restrict__ C, int M, int Nc, int K)
{
    __shared__ float As[16][65];
    __shared__ float Bs[16][65];
    int bm = blockIdx.y * 64, bn = blockIdx.x * 64;
    int tid = threadIdx.x;
    int tx = tid & 15, ty = tid >> 4;
    float acc[4][4] = {};
    for (int k0 = 0; k0 < K; k0 += 16) {
        #pragma unroll
        for (int i = 0; i < 4; i++) {
            int e = tid + i * 256; int r = e >> 4, kk = e & 15;
            As[kk][r] = A[(size_t)(bm + r) * K + k0 + kk];
        }
        #pragma unroll
        for (int i = 0; i < 4; i++) {
            int e = tid + i * 256; int kk = e >> 6, c = e & 63;
            Bs[kk][c] = B[(size_t)(k0 + kk) * Nc + bn + c];
        }
        __syncthreads();
        #pragma unroll
        for (int kk = 0; kk < 16; kk++) {
            float a0[4], b0[4];
            #pragma unroll
            for (int i = 0; i < 4; i++) a0[i] = As[kk][ty + i * 16];
            #pragma unroll
            for (int j = 0; j < 4; j++) b0[j] = Bs[kk][tx + j * 16];
            #pragma unroll
            for (int i = 0; i < 4; i++)
                #pragma unroll
                for (int j = 0; j < 4; j++)
                    acc[i][j] = fmaf(a0[i], b0[j], acc[i][j]);
        }
        __syncthreads();
    }
    #pragma unroll
    for (int i = 0; i < 4; i++) {
        int r = bm + ty + i * 16;
        #pragma unroll
        for (int j = 0; j < 4; j++) {
            int c = bn + tx + j * 16;
            float v = acc[i][j] + bias[c];
            if (RELU) v = fmaxf(v, 0.f);
            C[(size_t)r * Nc + c] = v;
        }
    }
}

// ---------------- SGEMM NT: C[M,Nn] = alpha * A[M,K] @ B[Nn,K]^T ----------------
__global__ __launch_bounds__(256) void gemm_nt(
    const float* __restrict__ A, const float* __restrict__ B,
    float* __restrict__ C, int M, int Nn, int K, float alpha)
{
    __shared__ float As[16][65];
    __shared__ float Bs[16][65];
    int bm = blockIdx.y * 64, bn = blockIdx.x * 64;
    int tid = threadIdx.x;
    int tx = tid & 15, ty = tid >> 4;
    float acc[4][4] = {};
    for (int k0 = 0; k0 < K; k0 += 16) {
        #pragma unroll
        for (int i = 0; i < 4; i++) {
            int e = tid + i * 256; int r = e >> 4, kk = e & 15;
            As[kk][r] = A[(size_t)(bm + r) * K + k0 + kk];
        }
        #pragma unroll
        for (int i = 0; i < 4; i++) {
            int e = tid + i * 256; int r = e >> 4, kk = e & 15;
            Bs[kk][r] = B[(size_t)(bn + r) * K + k0 + kk];
        }
        __syncthreads();
        #pragma unroll
        for (int kk = 0; kk < 16; kk++) {
            float a0[4], b0[4];
            #pragma unroll
            for (int i = 0; i < 4; i++) a0[i] = As[kk][ty + i * 16];
            #pragma unroll
            for (int j = 0; j < 4; j++) b0[j] = Bs[kk][tx + j * 16];
            #pragma unroll
            for (int i = 0; i < 4; i++)
                #pragma unroll
                for (int j = 0; j < 4; j++)
                    acc[i][j] = fmaf(a0[i], b0[j], acc[i][j]);
        }
        __syncthreads();
    }
    #pragma unroll
    for (int i = 0; i < 4; i++) {
        int r = bm + ty + i * 16;
        #pragma unroll
        for (int j = 0; j < 4; j++) {
            int c = bn + tx + j * 16;
            C[(size_t)r * Nn + c] = alpha * acc[i][j];
        }
    }
}

// ---------------- copy e0 into first half of cat buffer ----------------
__global__ __launch_bounds__(256) void cat_copy_kernel(const float* __restrict__ e0, float* __restrict__ cat)
{
    int row = blockIdx.x;
    for (int c = threadIdx.x; c < DIM; c += blockDim.x)
        cat[(size_t)row * (2 * DIM) + c] = e0[(size_t)row * DIM + c];
}

// ---------------- per-row: softmax(dots) + eps, renorm, top-k mask, updates = attn @ v ----
// one block per edge row (512 rows), row length 8192
__global__ __launch_bounds__(256) void attn_update_kernel(
    const float* __restrict__ dots, const float* __restrict__ v,
    const int* __restrict__ kn_ptr, float* __restrict__ cat_out)
{
    __shared__ float sval[N_NODES];       // 32 KB
    __shared__ float shmf[32];
    __shared__ unsigned shmu[32];
    __shared__ int   sel_idx[128];
    __shared__ float sel_w[128];
    __shared__ unsigned scount, stie;

    int row = blockIdx.x;
    int k = kn_ptr[0];
    if (k > 128) k = 128;
    const float* dr = dots + (size_t)row * N_NODES;

    for (int i = threadIdx.x; i < N_NODES; i += blockDim.x) sval[i] = dr[i];
    __syncthreads();

    // softmax stats
    float m = -INFINITY;
    for (int i = threadIdx.x; i < N_NODES; i += blockDim.x) m = fmaxf(m, sval[i]);
    float rowmax = blockReduceMax(m, shmf);
    float s = 0.f;
    for (int i = threadIdx.x; i < N_NODES; i += blockDim.x) s += expf(sval[i] - rowmax);
    float sumexp = blockReduceSum(s, shmf);
    float invsum = 1.f / sumexp;

    // exact k-th largest via bitwise bisection on monotone keys
    unsigned lo = 0u, hi = 0xFFFFFFFFu;
    while (lo < hi) {
        unsigned mid = lo + ((hi - lo) >> 1) + ((hi - lo) & 1u);   // ceil midpoint
        unsigned c = 0;
        for (int i = threadIdx.x; i < N_NODES; i += blockDim.x)
            if (fkey(sval[i]) >= mid) c++;
        c = blockReduceSumU(c, shmu);
        if (c >= (unsigned)k) lo = mid; else hi = mid - 1u;
    }
    unsigned Tth = lo;

    if (threadIdx.x == 0) { scount = 0u; }
    __syncthreads();
    for (int i = threadIdx.x; i < N_NODES; i += blockDim.x) {
        if (fkey(sval[i]) > Tth) {
            unsigned p = atomicAdd(&scount, 1u);
            if (p < (unsigned)k) sel_idx[p] = i;
        }
    }
    __syncthreads();
    if (threadIdx.x == 0) stie = scount;
    __syncthreads();
    for (int i = threadIdx.x; i < N_NODES; i += blockDim.x) {
        if (fkey(sval[i]) == Tth) {
            unsigned p = atomicAdd(&stie, 1u);
            if (p < (unsigned)k) sel_idx[p] = i;
        }
    }
    __syncthreads();

    // weights: a = (softmax + eps) / (1 + N*eps)
    float renorm = 1.f / (1.f + (float)N_NODES * 1e-8f);
    for (int sI = threadIdx.x; sI < k; sI += blockDim.x) {
        int idx = sel_idx[sI];
        sel_w[sI] = (expf(sval[idx] - rowmax) * invsum + 1e-8f) * renorm;
    }
    __syncthreads();

    // updates row = sum_sel w * v[idx,:]  -> second half of cat buffer
    float acc[4] = {0.f, 0.f, 0.f, 0.f};
    for (int sI = 0; sI < k; sI++) {
        int idx = sel_idx[sI];
        float w = sel_w[sI];
        const float* vr = v + (size_t)idx * DIM;
        #pragma unroll
        for (int j = 0; j < 4; j++)
            acc[j] = fmaf(w, __ldg(vr + threadIdx.x + j * 256), acc[j]);
    }
    #pragma unroll
    for (int j = 0; j < 4; j++)
        cat_out[(size_t)row * (2 * DIM) + DIM + threadIdx.x + j * 256] = acc[j];
}

// ---------------- per-row: H = mask_topk(softmax(dots_v), k_e), row length 512 ----------------
__global__ __launch_bounds__(128) void h_kernel(
    const float* __restrict__ dv, const int* __restrict__ ke_ptr, float* __restrict__ Hout)
{
    __shared__ float sval[N_EDGE];
    __shared__ float shmf[32];
    __shared__ unsigned shmu[32];
    __shared__ unsigned scount, stie;

    int row = blockIdx.x;
    int k = ke_ptr[0];
    if (k > 128) k = 128;
    const float* dr = dv + (size_t)row * N_EDGE;
    for (int i = threadIdx.x; i < N_EDGE; i += blockDim.x) sval[i] = dr[i];
    __syncthreads();

    float m = -INFINITY;
    for (int i = threadIdx.x; i < N_EDGE; i += blockDim.x) m = fmaxf(m, sval[i]);
    float rowmax = blockReduceMax(m, shmf);
    float s = 0.f;
    for (int i = threadIdx.x; i < N_EDGE; i += blockDim.x) s += expf(sval[i] - rowmax);
    float sumexp = blockReduceSum(s, shmf);
    float invsum = 1.f / sumexp;

    unsigned lo = 0u, hi = 0xFFFFFFFFu;
    while (lo < hi) {
        unsigned mid = lo + ((hi - lo) >> 1) + ((hi - lo) & 1u);
        unsigned c = 0;
        for (int i = threadIdx.x; i < N_EDGE; i += blockDim.x)
            if (fkey(sval[i]) >= mid) c++;
        c = blockReduceSumU(c, shmu);
        if (c >= (unsigned)k) lo = mid; else hi = mid - 1u;
    }
    unsigned Tth = lo;

    // count strictly-greater, allocate tie slots
    unsigned cg = 0;
    for (int i = threadIdx.x; i < N_EDGE; i += blockDim.x)
        if (fkey(sval[i]) > Tth) cg++;
    unsigned cnt_gt = blockReduceSumU(cg, shmu);
    unsigned needed = (unsigned)k - cnt_gt;
    if (threadIdx.x == 0) { scount = 0u; stie = 0u; }
    __syncthreads();

    float* hr = Hout + (size_t)row * N_EDGE;
    for (int i = threadIdx.x; i < N_EDGE; i += blockDim.x) {
        unsigned ky = fkey(sval[i]);
        bool sel = false;
        if (ky > Tth) sel = true;
        else if (ky == Tth) {
            unsigned p = atomicAdd(&stie, 1u);
            sel = (p < needed);
        }
        hr[i] = sel ? expf(sval[i] - rowmax) * invsum : 0.f;
    }
}

// ---------------- launch ----------------
extern "C" void kernel_launch(void* const* d_in, const int* in_sizes, int n_in,
                              void* d_out, int out_size)
{
    const float* inputs  = (const float*)d_in[0];
    const float* noise   = (const float*)d_in[1];
    const float* emu     = (const float*)d_in[2];
    const float* elogsig = (const float*)d_in[3];
    const float* Wq = (const float*)d_in[4];  const float* bq = (const float*)d_in[5];
    const float* Wk = (const float*)d_in[6];  const float* bk = (const float*)d_in[7];
    const float* Wv = (const float*)d_in[8];  const float* bv = (const float*)d_in[9];
    const float* W1 = (const float*)d_in[10]; const float* b1 = (const float*)d_in[11];
    const float* W2 = (const float*)d_in[12]; const float* b2 = (const float*)d_in[13];
    const float* g_in = (const float*)d_in[14]; const float* b_in = (const float*)d_in[15];
    const float* g_e  = (const float*)d_in[16]; const float* b_e  = (const float*)d_in[17];
    const int* kn = (const int*)d_in[18];
    const int* ke = (const int*)d_in[19];

    float* out = (float*)d_out;
    float* out_edges = out + E_OFF;
    float* out_H     = out + H_OFF;
    float* out_dots  = out + DOTS_OFF;

    float* px  = nullptr; cudaGetSymbolAddress((void**)&px,  g_x);
    float* pk  = nullptr; cudaGetSymbolAddress((void**)&pk,  g_k);
    float* pv  = nullptr; cudaGetSymbolAddress((void**)&pv,  g_v);
    float* pq2 = nullptr; cudaGetSymbolAddress((void**)&pq2, g_q2);
    float* pe0 = nullptr; cudaGetSymbolAddress((void**)&pe0, g_e0);
    float* pq  = nullptr; cudaGetSymbolAddress((void**)&pq,  g_q);
    float* pcat= nullptr; cudaGetSymbolAddress((void**)&pcat,g_cat);
    float* ph1 = nullptr; cudaGetSymbolAddress((void**)&ph1, g_h1);
    float* pk2 = nullptr; cudaGetSymbolAddress((void**)&pk2, g_k2);
    float* pdv = nullptr; cudaGetSymbolAddress((void**)&pdv, g_dv);

    const float scale = 1.0f / 32.0f;  // 1024^-0.5

    // 1) x = LN(inputs); e0 = LN(mu + exp(ls)*noise)
    ln_kernel<<<N_NODES, 256>>>(inputs, g_in, b_in, px, DIM);
    edge_ln_kernel<<<N_EDGE, 256>>>(noise, emu, elogsig, g_e, b_e, pe0);

    // 2) big node-side GEMMs
    {
        dim3 grid(DIM / 64, N_NODES / 64);
        gemm_nn<1><<<grid, 256>>>(px, Wk, bk, pk,  N_NODES, DIM, DIM);
        gemm_nn<1><<<grid, 256>>>(px, Wv, bv, pv,  N_NODES, DIM, DIM);
        gemm_nn<0><<<grid, 256>>>(px, Wq, bq, pq2, N_NODES, DIM, DIM);
    }
    // 3) q = relu(e0 @ Wq + bq)
    {
        dim3 grid(DIM / 64, N_EDGE / 64);
        gemm_nn<1><<<grid, 256>>>(pe0, Wq, bq, pq, N_EDGE, DIM, DIM);
    }
    // 4) dots = q @ k^T * scale  -> straight into output
    {
        dim3 grid(N_NODES / 64, N_EDGE / 64);
        gemm_nt<<<grid, 256>>>(pq, pk, out_dots, N_EDGE, N_NODES, DIM, scale);
    }
    // 5) cat = [e0 | updates]; updates via sparse top-k attention
    cat_copy_kernel<<<N_EDGE, 256>>>(pe0, pcat);
    attn_update_kernel<<<N_EDGE, 256>>>(out_dots, pv, kn, pcat);

    // 6) MLP: h1 = relu(cat @ W1 + b1); edges_out = h1 @ W2 + b2
    {
        dim3 grid(HID / 64, N_EDGE / 64);
        gemm_nn<1><<<grid, 256>>>(pcat, W1, b1, ph1, N_EDGE, HID, 2 * DIM);
    }
    {
        dim3 grid(DIM / 64, N_EDGE / 64);
        gemm_nn<0><<<grid, 256>>>(ph1, W2, b2, out_edges, N_EDGE, DIM, DIM);
    }
    // 7) k2 = relu(edges_out @ Wk + bk)
    {
        dim3 grid(DIM / 64, N_EDGE / 64);
        gemm_nn<1><<<grid, 256>>>(out_edges, Wk, bk, pk2, N_EDGE, DIM, DIM);
    }
    // 8) dots_v = q2 @ k2^T * scale; H = mask_topk(softmax(dots_v), k_e)
    {
        dim3 grid(N_EDGE / 64, N_NODES / 64);
        gemm_nt<<<grid, 256>>>(pq2, pk2, pdv, N_NODES, N_EDGE, DIM, scale);
    }
    h_kernel<<<N_NODES, 128>>>(pdv, ke, out_H);
}

// round 8
// speedup vs baseline: 1.8802x; 1.8802x over previous
#include <cuda_runtime.h>
#include <cuda_bf16.h>
#include <math.h>
#include <stdint.h>

#define N_NODES 8192
#define N_EDGE  512
#define DIM     1024
#define HIDD    1024

// output float offsets: (edges, H, dots)
#define E_OFF 0
#define H_OFF (N_EDGE * DIM)                 // 524288
#define DOTS_OFF (H_OFF + N_NODES * N_EDGE)  // 4718592

// ==================== small helpers ====================
__device__ __forceinline__ uint32_t smem_u32(const void* p) {
    uint32_t a;
    asm("{ .reg .u64 t; cvta.to.shared.u64 t, %1; cvt.u32.u64 %0, t; }" : "=r"(a) : "l"(p));
    return a;
}
__device__ __forceinline__ void cp16(uint32_t dst, const void* src) {
    asm volatile("cp.async.cg.shared.global [%0], [%1], 16;" :: "r"(dst), "l"(src));
}
#define CP_COMMIT() asm volatile("cp.async.commit_group;" ::: "memory")
#define CP_WAIT0()  asm volatile("cp.async.wait_group 0;" ::: "memory")
#define CP_WAIT1()  asm volatile("cp.async.wait_group 1;" ::: "memory")

__device__ __forceinline__ void ldsm_x4(uint32_t* r, uint32_t addr) {
    asm volatile("ldmatrix.sync.aligned.m8n8.x4.shared.b16 {%0,%1,%2,%3}, [%4];"
                 : "=r"(r[0]), "=r"(r[1]), "=r"(r[2]), "=r"(r[3]) : "r"(addr));
}
__device__ __forceinline__ void mma_bf16(float* c, const uint32_t* a, const uint32_t* b) {
    asm volatile("mma.sync.aligned.m16n8k16.row.col.f32.bf16.bf16.f32 "
                 "{%0,%1,%2,%3}, {%4,%5,%6,%7}, {%8,%9}, {%0,%1,%2,%3};"
                 : "+f"(c[0]), "+f"(c[1]), "+f"(c[2]), "+f"(c[3])
                 : "r"(a[0]), "r"(a[1]), "r"(a[2]), "r"(a[3]), "r"(b[0]), "r"(b[1]));
}

// 3-way split: v = h + m + l  (8+8+8 mantissa bits; ensures full fp32 coverage)
__device__ __forceinline__ void split3(float v, __nv_bfloat16& h, __nv_bfloat16& m, __nv_bfloat16& l) {
    h = __float2bfloat16_rn(v);
    float r1 = v - __bfloat162float(h);
    m = __float2bfloat16_rn(r1);
    l = __float2bfloat16_rn(r1 - __bfloat162float(m));
}
__device__ __forceinline__ unsigned fkey(float f) {
    unsigned u = __float_as_uint(f);
    return u ^ (((int)u >> 31) | 0x80000000u);
}

// ==================== scratch (static device memory) ====================
__device__ __nv_bfloat16 g_xh [N_NODES * DIM], g_xm [N_NODES * DIM], g_xl [N_NODES * DIM];
__device__ __nv_bfloat16 g_kh [N_NODES * DIM], g_km [N_NODES * DIM], g_kl [N_NODES * DIM];
__device__ __nv_bfloat16 g_q2h[N_NODES * DIM], g_q2m[N_NODES * DIM], g_q2l[N_NODES * DIM];
__device__ float         g_vf [N_NODES * DIM];
__device__ float         g_dv [N_NODES * N_EDGE];
__device__ __nv_bfloat16 g_e0h[N_EDGE * DIM], g_e0m[N_EDGE * DIM], g_e0l[N_EDGE * DIM];
__device__ __nv_bfloat16 g_qh [N_EDGE * DIM], g_qm [N_EDGE * DIM], g_ql [N_EDGE * DIM];
__device__ __nv_bfloat16 g_cth[N_EDGE * 2 * DIM], g_ctm[N_EDGE * 2 * DIM], g_ctl[N_EDGE * 2 * DIM];
__device__ __nv_bfloat16 g_h1h[N_EDGE * HIDD], g_h1m[N_EDGE * HIDD], g_h1l[N_EDGE * HIDD];
__device__ __nv_bfloat16 g_eh [N_EDGE * DIM], g_em [N_EDGE * DIM], g_el [N_EDGE * DIM];
__device__ __nv_bfloat16 g_k2h[N_EDGE * DIM], g_k2m[N_EDGE * DIM], g_k2l[N_EDGE * DIM];
// transposed weights (bf16 triple): T[N][K]
__device__ __nv_bfloat16 g_WqTh[DIM * DIM], g_WqTm[DIM * DIM], g_WqTl[DIM * DIM];
__device__ __nv_bfloat16 g_WkTh[DIM * DIM], g_WkTm[DIM * DIM], g_WkTl[DIM * DIM];
__device__ __nv_bfloat16 g_WvTh[DIM * DIM], g_WvTm[DIM * DIM], g_WvTl[DIM * DIM];
__device__ __nv_bfloat16 g_W1Th[HIDD * 2 * DIM], g_W1Tm[HIDD * 2 * DIM], g_W1Tl[HIDD * 2 * DIM];
__device__ __nv_bfloat16 g_W2Th[DIM * HIDD], g_W2Tm[DIM * HIDD], g_W2Tl[DIM * HIDD];

// ==================== reductions ====================
__device__ __forceinline__ float blockReduceSum(float val, float* shm) {
    int lane = threadIdx.x & 31, wid = threadIdx.x >> 5;
    #pragma unroll
    for (int o = 16; o > 0; o >>= 1) val += __shfl_down_sync(0xffffffffu, val, o);
    if (lane == 0) shm[wid] = val;
    __syncthreads();
    int nw = (blockDim.x + 31) >> 5;
    val = (threadIdx.x < nw) ? shm[threadIdx.x] : 0.f;
    if (wid == 0) {
        #pragma unroll
        for (int o = 16; o > 0; o >>= 1) val += __shfl_down_sync(0xffffffffu, val, o);
        if (lane == 0) shm[0] = val;
    }
    __syncthreads();
    float r = shm[0];
    __syncthreads();
    return r;
}
__device__ __forceinline__ float blockReduceMax(float val, float* shm) {
    int lane = threadIdx.x & 31, wid = threadIdx.x >> 5;
    #pragma unroll
    for (int o = 16; o > 0; o >>= 1) val = fmaxf(val, __shfl_down_sync(0xffffffffu, val, o));
    if (lane == 0) shm[wid] = val;
    __syncthreads();
    int nw = (blockDim.x + 31) >> 5;
    val = (threadIdx.x < nw) ? shm[threadIdx.x] : -INFINITY;
    if (wid == 0) {
        #pragma unroll
        for (int o = 16; o > 0; o >>= 1) val = fmaxf(val, __shfl_down_sync(0xffffffffu, val, o));
        if (lane == 0) shm[0] = val;
    }
    __syncthreads();
    float r = shm[0];
    __syncthreads();
    return r;
}
__device__ __forceinline__ unsigned blockReduceSumU(unsigned val, unsigned* shm) {
    int lane = threadIdx.x & 31, wid = threadIdx.x >> 5;
    #pragma unroll
    for (int o = 16; o > 0; o >>= 1) val += __shfl_down_sync(0xffffffffu, val, o);
    if (lane == 0) shm[wid] = val;
    __syncthreads();
    int nw = (blockDim.x + 31) >> 5;
    val = (threadIdx.x < nw) ? shm[threadIdx.x] : 0u;
    if (wid == 0) {
        #pragma unroll
        for (int o = 16; o > 0; o >>= 1) val += __shfl_down_sync(0xffffffffu, val, o);
        if (lane == 0) shm[0] = val;
    }
    __syncthreads();
    unsigned r = shm[0];
    __syncthreads();
    return r;
}

// ==================== layernorm -> bf16 triple ====================
__global__ __launch_bounds__(256) void ln_kernel(
    const float* __restrict__ in, const float* __restrict__ g, const float* __restrict__ b,
    __nv_bfloat16* __restrict__ oh, __nv_bfloat16* __restrict__ om, __nv_bfloat16* __restrict__ ol)
{
    __shared__ float shm[32];
    int row = blockIdx.x;
    const float* x = in + (size_t)row * DIM;
    float s = 0.f, s2 = 0.f;
    for (int i = threadIdx.x; i < DIM; i += blockDim.x) { float v = x[i]; s += v; s2 += v * v; }
    float S  = blockReduceSum(s,  shm);
    float S2 = blockReduceSum(s2, shm);
    float mean = S / DIM;
    float var  = S2 / DIM - mean * mean;
    float inv  = rsqrtf(var + 1e-5f);
    for (int i = threadIdx.x; i < DIM; i += blockDim.x) {
        float y = (x[i] - mean) * inv * g[i] + b[i];
        __nv_bfloat16 h, m, l; split3(y, h, m, l);
        size_t o = (size_t)row * DIM + i;
        oh[o] = h; om[o] = m; ol[o] = l;
    }
}

__global__ __launch_bounds__(256) void edge_ln_kernel(
    const float* __restrict__ noise, const float* __restrict__ mu, const float* __restrict__ ls,
    const float* __restrict__ g, const float* __restrict__ b,
    __nv_bfloat16* __restrict__ e0h, __nv_bfloat16* __restrict__ e0m, __nv_bfloat16* __restrict__ e0l,
    __nv_bfloat16* __restrict__ cth, __nv_bfloat16* __restrict__ ctm, __nv_bfloat16* __restrict__ ctl)
{
    __shared__ float shm[32];
    int row = blockIdx.x;
    const float* nz = noise + (size_t)row * DIM;
    float s = 0.f, s2 = 0.f;
    for (int i = threadIdx.x; i < DIM; i += blockDim.x) {
        float v = mu[i] + expf(ls[i]) * nz[i];
        s += v; s2 += v * v;
    }
    float S  = blockReduceSum(s,  shm);
    float S2 = blockReduceSum(s2, shm);
    float mean = S / DIM;
    float var  = S2 / DIM - mean * mean;
    float inv  = rsqrtf(var + 1e-5f);
    for (int i = threadIdx.x; i < DIM; i += blockDim.x) {
        float v = mu[i] + expf(ls[i]) * nz[i];
        float y = (v - mean) * inv * g[i] + b[i];
        __nv_bfloat16 h, m, l; split3(y, h, m, l);
        size_t o = (size_t)row * DIM + i;
        e0h[o] = h; e0m[o] = m; e0l[o] = l;
        size_t oc = (size_t)row * 2 * DIM + i;
        cth[oc] = h; ctm[oc] = m; ctl[oc] = l;
    }
}

// ==================== weight transpose + convert: T[N][K] = W[K][N] ====================
__global__ __launch_bounds__(256) void transpose_conv(
    const float* __restrict__ W,
    __nv_bfloat16* __restrict__ Th, __nv_bfloat16* __restrict__ Tm, __nv_bfloat16* __restrict__ Tl,
    int R, int C)  // W is [R][C]
{
    __shared__ float t[32][33];
    int c0 = blockIdx.x * 32, r0 = blockIdx.y * 32;
    #pragma unroll
    for (int i = threadIdx.y; i < 32; i += 8)
        t[i][threadIdx.x] = W[(size_t)(r0 + i) * C + c0 + threadIdx.x];
    __syncthreads();
    #pragma unroll
    for (int i = threadIdx.y; i < 32; i += 8) {
        float v = t[threadIdx.x][i];   // W[r0+tx][c0+i]
        __nv_bfloat16 h, m, l; split3(v, h, m, l);
        size_t o = (size_t)(c0 + i) * R + r0 + threadIdx.x;
        Th[o] = h; Tm[o] = m; Tl[o] = l;
    }
}

// ==================== 6-term split HMMA GEMM with RN chunk-flush ====================
// Chunk accumulators start at 0 each BK-chunk (limits tensor-core RZ accumulation error);
// master accumulation happens in fp32 FADD (round-to-nearest).
#define BK 32
#define PADK 40            // BK + 8 elems -> 80B row stride, conflict-free ldmatrix

template<int TBM, int TBN, int TWM, int TWN>
__global__ __launch_bounds__(256) void gemm6(
    const __nv_bfloat16* __restrict__ Ah, const __nv_bfloat16* __restrict__ Am, const __nv_bfloat16* __restrict__ Al,
    const __nv_bfloat16* __restrict__ Bh, const __nv_bfloat16* __restrict__ Bm, const __nv_bfloat16* __restrict__ Bl,
    const float* __restrict__ bias, float alpha, int relu,
    float* __restrict__ Cf,
    __nv_bfloat16* __restrict__ Ch, __nv_bfloat16* __restrict__ Cm, __nv_bfloat16* __restrict__ Cl,
    int M, int N, int K)
{
    constexpr int WMC  = TBM / TWM;          // warps along M
    constexpr int MI   = TWM / 16;
    constexpr int NJ   = TWN / 8;
    constexpr int NJ2  = TWN / 16;
    constexpr int TILEA = TBM * PADK * 2;
    constexpr int TILEB = TBN * PADK * 2;
    constexpr int STAGE = 3 * (TILEA + TILEB);

    extern __shared__ char smem[];
    const uint32_t sb = smem_u32(smem);
    const int tid = threadIdx.x;
    const int lane = tid & 31, wid = tid >> 5;
    const int warp_m = wid % WMC, warp_n = wid / WMC;
    const int bm = blockIdx.y * TBM, bn = blockIdx.x * TBN;

    float master[MI][NJ][4];
    #pragma unroll
    for (int i = 0; i < MI; i++)
        #pragma unroll
        for (int j = 0; j < NJ; j++)
            #pragma unroll
            for (int t = 0; t < 4; t++) master[i][j][t] = 0.f;

    const int NC = K / BK;

    auto issue_load = [&](int kc, int stage) {
        uint32_t base = sb + stage * STAGE;
        const __nv_bfloat16* as[3] = {Ah, Am, Al};
        const __nv_bfloat16* bs[3] = {Bh, Bm, Bl};
        #pragma unroll
        for (int t = 0; t < 3; t++) {
            for (int id = tid; id < TBM * 4; id += 256) {
                int row = id >> 2, c = id & 3;
                uint32_t so = (uint32_t)(row * (PADK * 2) + c * 16);
                cp16(base + t * TILEA + so, as[t] + (size_t)(bm + row) * K + (size_t)kc * BK + c * 8);
            }
            for (int id = tid; id < TBN * 4; id += 256) {
                int row = id >> 2, c = id & 3;
                uint32_t so = (uint32_t)(row * (PADK * 2) + c * 16);
                cp16(base + 3 * TILEA + t * TILEB + so, bs[t] + (size_t)(bn + row) * K + (size_t)kc * BK + c * 8);
            }
        }
    };

    issue_load(0, 0);
    CP_COMMIT();

    const int arow = lane & 15;
    const int acol8 = lane >> 4;
    const int bg = lane >> 3, br = lane & 7;
    const int bnrow = ((bg & 2) ? 8 : 0) + br;
    const int bkoff = (bg & 1) ? 8 : 0;

    for (int kc = 0; kc < NC; kc++) {
        if (kc + 1 < NC) {
            issue_load(kc + 1, (kc + 1) & 1);
            CP_COMMIT();
            CP_WAIT1();
        } else {
            CP_WAIT0();
        }
        __syncthreads();

        uint32_t base = sb + (kc & 1) * STAGE;
        uint32_t sAh = base, sAm = base + TILEA, sAl = base + 2 * TILEA;
        uint32_t sBh = base + 3 * TILEA, sBm = sBh + TILEB, sBl = sBh + 2 * TILEB;

        // fresh chunk accumulator (tensor-core RZ chain limited to this chunk)
        float chunk[MI][NJ][4];
        #pragma unroll
        for (int i = 0; i < MI; i++)
            #pragma unroll
            for (int j = 0; j < NJ; j++)
                #pragma unroll
                for (int t = 0; t < 4; t++) chunk[i][j][t] = 0.f;

        #pragma unroll
        for (int ks = 0; ks < 2; ks++) {
            int k0 = ks * 16;
            uint32_t ah[MI][4], am[MI][4], al[MI][4];
            #pragma unroll
            for (int mi = 0; mi < MI; mi++) {
                uint32_t roff = (uint32_t)((warp_m * TWM + mi * 16 + arow) * (PADK * 2)
                                           + (k0 + acol8 * 8) * 2);
                ldsm_x4(ah[mi], sAh + roff);
                ldsm_x4(am[mi], sAm + roff);
                ldsm_x4(al[mi], sAl + roff);
            }
            uint32_t bh[NJ][2], bmm[NJ][2], bl[NJ][2];
            #pragma unroll
            for (int nj2 = 0; nj2 < NJ2; nj2++) {
                uint32_t roff = (uint32_t)((warp_n * TWN + nj2 * 16 + bnrow) * (PADK * 2)
                                           + (k0 + bkoff) * 2);
                uint32_t r4[4];
                ldsm_x4(r4, sBh + roff);
                bh[nj2 * 2][0] = r4[0]; bh[nj2 * 2][1] = r4[1];
                bh[nj2 * 2 + 1][0] = r4[2]; bh[nj2 * 2 + 1][1] = r4[3];
                ldsm_x4(r4, sBm + roff);
                bmm[nj2 * 2][0] = r4[0]; bmm[nj2 * 2][1] = r4[1];
                bmm[nj2 * 2 + 1][0] = r4[2]; bmm[nj2 * 2 + 1][1] = r4[3];
                ldsm_x4(r4, sBl + roff);
                bl[nj2 * 2][0] = r4[0]; bl[nj2 * 2][1] = r4[1];
                bl[nj2 * 2 + 1][0] = r4[2]; bl[nj2 * 2 + 1][1] = r4[3];
            }
            #pragma unroll
            for (int mi = 0; mi < MI; mi++) {
                #pragma unroll
                for (int nj = 0; nj < NJ; nj++) {
                    mma_bf16(chunk[mi][nj], ah[mi], bh[nj]);   // hh
                    mma_bf16(chunk[mi][nj], ah[mi], bmm[nj]);  // hm
                    mma_bf16(chunk[mi][nj], am[mi], bh[nj]);   // mh
                    mma_bf16(chunk[mi][nj], ah[mi], bl[nj]);   // hl
                    mma_bf16(chunk[mi][nj], al[mi], bh[nj]);   // lh
                    mma_bf16(chunk[mi][nj], am[mi], bmm[nj]);  // mm
                }
            }
        }
        // RN flush to master (FFMA pipe, round-to-nearest)
        #pragma unroll
        for (int i = 0; i < MI; i++)
            #pragma unroll
            for (int j = 0; j < NJ; j++)
                #pragma unroll
                for (int t = 0; t < 4; t++) master[i][j][t] += chunk[i][j][t];
        __syncthreads();
    }

    // ---- epilogue ----
    int gid = lane >> 2, qid = lane & 3;
    #pragma unroll
    for (int mi = 0; mi < MI; mi++) {
        #pragma unroll
        for (int nj = 0; nj < NJ; nj++) {
            int n0 = bn + warp_n * TWN + nj * 8 + qid * 2;
            float bv0 = bias ? bias[n0] : 0.f;
            float bv1 = bias ? bias[n0 + 1] : 0.f;
            #pragma unroll
            for (int half = 0; half < 2; half++) {
                int mrow = bm + warp_m * TWM + mi * 16 + gid + half * 8;
                float v0 = master[mi][nj][half * 2 + 0] * alpha + bv0;
                float v1 = master[mi][nj][half * 2 + 1] * alpha + bv1;
                if (relu) { v0 = fmaxf(v0, 0.f); v1 = fmaxf(v1, 0.f); }
                size_t o = (size_t)mrow * N + n0;
                if (Cf) *(float2*)(Cf + o) = make_float2(v0, v1);
                if (Ch) {
                    __nv_bfloat16 h0, m0, l0, h1, m1, l1;
                    split3(v0, h0, m0, l0);
                    split3(v1, h1, m1, l1);
                    __nv_bfloat162 hp; hp.x = h0; hp.y = h1;
                    __nv_bfloat162 mp; mp.x = m0; mp.y = m1;
                    __nv_bfloat162 lp; lp.x = l0; lp.y = l1;
                    *(__nv_bfloat162*)(Ch + o) = hp;
                    *(__nv_bfloat162*)(Cm + o) = mp;
                    *(__nv_bfloat162*)(Cl + o) = lp;
                }
            }
        }
    }
}

// ==================== attn row: softmax+eps+renorm, top-k, sparse update ====================
__global__ __launch_bounds__(256) void attn_update_kernel(
    const float* __restrict__ dots, const float* __restrict__ v,
    const int* __restrict__ kn_ptr,
    __nv_bfloat16* __restrict__ cth, __nv_bfloat16* __restrict__ ctm, __nv_bfloat16* __restrict__ ctl)
{
    __shared__ float sval[N_NODES];
    __shared__ float shmf[32];
    __shared__ unsigned shmu[32];
    __shared__ int   sel_idx[128];
    __shared__ float sel_w[128];
    __shared__ unsigned scount, stie;

    int row = blockIdx.x;
    int k = kn_ptr[0];
    if (k > 128) k = 128;
    const float* dr = dots + (size_t)row * N_NODES;

    for (int i = threadIdx.x; i < N_NODES; i += blockDim.x) sval[i] = dr[i];
    __syncthreads();

    float m = -INFINITY;
    for (int i = threadIdx.x; i < N_NODES; i += blockDim.x) m = fmaxf(m, sval[i]);
    float rowmax = blockReduceMax(m, shmf);
    float s = 0.f;
    for (int i = threadIdx.x; i < N_NODES; i += blockDim.x) s += expf(sval[i] - rowmax);
    float sumexp = blockReduceSum(s, shmf);
    float invsum = 1.f / sumexp;

    unsigned lo = 0u, hi = 0xFFFFFFFFu;
    while (lo < hi) {
        unsigned mid = lo + ((hi - lo) >> 1) + ((hi - lo) & 1u);
        unsigned c = 0;
        for (int i = threadIdx.x; i < N_NODES; i += blockDim.x)
            if (fkey(sval[i]) >= mid) c++;
        c = blockReduceSumU(c, shmu);
        if (c >= (unsigned)k) lo = mid; else hi = mid - 1u;
    }
    unsigned Tth = lo;

    if (threadIdx.x == 0) scount = 0u;
    __syncthreads();
    for (int i = threadIdx.x; i < N_NODES; i += blockDim.x) {
        if (fkey(sval[i]) > Tth) {
            unsigned p = atomicAdd(&scount, 1u);
            if (p < (unsigned)k) sel_idx[p] = i;
        }
    }
    __syncthreads();
    if (threadIdx.x == 0) stie = scount;
    __syncthreads();
    for (int i = threadIdx.x; i < N_NODES; i += blockDim.x) {
        if (fkey(sval[i]) == Tth) {
            unsigned p = atomicAdd(&stie, 1u);
            if (p < (unsigned)k) sel_idx[p] = i;
        }
    }
    __syncthreads();

    float renorm = 1.f / (1.f + (float)N_NODES * 1e-8f);
    for (int sI = threadIdx.x; sI < k; sI += blockDim.x) {
        int idx = sel_idx[sI];
        sel_w[sI] = (expf(sval[idx] - rowmax) * invsum + 1e-8f) * renorm;
    }
    __syncthreads();

    float acc[4] = {0.f, 0.f, 0.f, 0.f};
    for (int sI = 0; sI < k; sI++) {
        int idx = sel_idx[sI];
        float w = sel_w[sI];
        const float* vr = v + (size_t)idx * DIM;
        #pragma unroll
        for (int j = 0; j < 4; j++)
            acc[j] = fmaf(w, __ldg(vr + threadIdx.x + j * 256), acc[j]);
    }
    #pragma unroll
    for (int j = 0; j < 4; j++) {
        __nv_bfloat16 h, mm2, l; split3(acc[j], h, mm2, l);
        size_t o = (size_t)row * 2 * DIM + DIM + threadIdx.x + j * 256;
        cth[o] = h; ctm[o] = mm2; ctl[o] = l;
    }
}

// ==================== H = mask_topk(softmax(dots_v), k_e) ====================
__global__ __launch_bounds__(128) void h_kernel(
    const float* __restrict__ dv, const int* __restrict__ ke_ptr, float* __restrict__ Hout)
{
    __shared__ float sval[N_EDGE];
    __shared__ float shmf[32];
    __shared__ unsigned shmu[32];
    __shared__ unsigned stie;

    int row = blockIdx.x;
    int k = ke_ptr[0];
    if (k > 128) k = 128;
    const float* dr = dv + (size_t)row * N_EDGE;
    for (int i = threadIdx.x; i < N_EDGE; i += blockDim.x) sval[i] = dr[i];
    __syncthreads();

    float m = -INFINITY;
    for (int i = threadIdx.x; i < N_EDGE; i += blockDim.x) m = fmaxf(m, sval[i]);
    float rowmax = blockReduceMax(m, shmf);
    float s = 0.f;
    for (int i = threadIdx.x; i < N_EDGE; i += blockDim.x) s += expf(sval[i] - rowmax);
    float sumexp = blockReduceSum(s, shmf);
    float invsum = 1.f / sumexp;

    unsigned lo = 0u, hi = 0xFFFFFFFFu;
    while (lo < hi) {
        unsigned mid = lo + ((hi - lo) >> 1) + ((hi - lo) & 1u);
        unsigned c = 0;
        for (int i = threadIdx.x; i < N_EDGE; i += blockDim.x)
            if (fkey(sval[i]) >= mid) c++;
        c = blockReduceSumU(c, shmu);
        if (c >= (unsigned)k) lo = mid; else hi = mid - 1u;
    }
    unsigned Tth = lo;

    unsigned cg = 0;
    for (int i = threadIdx.x; i < N_EDGE; i += blockDim.x)
        if (fkey(sval[i]) > Tth) cg++;
    unsigned cnt_gt = blockReduceSumU(cg, shmu);
    unsigned needed = (unsigned)k - cnt_gt;
    if (threadIdx.x == 0) stie = 0u;
    __syncthreads();

    float* hr = Hout + (size_t)row * N_EDGE;
    for (int i = threadIdx.x; i < N_EDGE; i += blockDim.x) {
        unsigned ky = fkey(sval[i]);
        bool sel = false;
        if (ky > Tth) sel = true;
        else if (ky == Tth) {
            unsigned p = atomicAdd(&stie, 1u);
            sel = (p < needed);
        }
        hr[i] = sel ? expf(sval[i] - rowmax) * invsum : 0.f;
    }
}

// ==================== launch ====================
#define SMEM_BIG   (2 * 3 * (64 * PADK * 2 + 128 * PADK * 2))   // 92160
#define SMEM_SMALL (2 * 3 * (32 * PADK * 2 + 128 * PADK * 2))   // 76800

extern "C" void kernel_launch(void* const* d_in, const int* in_sizes, int n_in,
                              void* d_out, int out_size)
{
    const float* inputs  = (const float*)d_in[0];
    const float* noise   = (const float*)d_in[1];
    const float* emu     = (const float*)d_in[2];
    const float* elogsig = (const float*)d_in[3];
    const float* Wq = (const float*)d_in[4];  const float* bq = (const float*)d_in[5];
    const float* Wk = (const float*)d_in[6];  const float* bk = (const float*)d_in[7];
    const float* Wv = (const float*)d_in[8];  const float* bv = (const float*)d_in[9];
    const float* W1 = (const float*)d_in[10]; const float* b1 = (const float*)d_in[11];
    const float* W2 = (const float*)d_in[12]; const float* b2 = (const float*)d_in[13];
    const float* gin = (const float*)d_in[14]; const float* bin = (const float*)d_in[15];
    const float* ge  = (const float*)d_in[16]; const float* be  = (const float*)d_in[17];
    const int* kn = (const int*)d_in[18];
    const int* ke = (const int*)d_in[19];

    float* out = (float*)d_out;
    float* out_edges = out + E_OFF;
    float* out_H     = out + H_OFF;
    float* out_dots  = out + DOTS_OFF;

    auto big   = gemm6<64, 128, 32, 32>;
    auto small = gemm6<32, 128, 16, 32>;
    cudaFuncSetAttribute(big,   cudaFuncAttributeMaxDynamicSharedMemorySize, SMEM_BIG);
    cudaFuncSetAttribute(small, cudaFuncAttributeMaxDynamicSharedMemorySize, SMEM_SMALL);

    __nv_bfloat16 *xh, *xm, *xl, *kh, *km, *kl, *q2h, *q2m, *q2l;
    __nv_bfloat16 *e0h, *e0m, *e0l, *qh, *qm, *ql, *cth, *ctm, *ctl;
    __nv_bfloat16 *h1h, *h1m, *h1l, *eh, *em, *el, *k2h, *k2m, *k2l;
    __nv_bfloat16 *wqh, *wqm, *wql, *wkh, *wkm, *wkl, *wvh, *wvm, *wvl;
    __nv_bfloat16 *w1h, *w1m, *w1l, *w2h, *w2m, *w2l;
    float *vf, *dv;
    cudaGetSymbolAddress((void**)&xh, g_xh);   cudaGetSymbolAddress((void**)&xm, g_xm);   cudaGetSymbolAddress((void**)&xl, g_xl);
    cudaGetSymbolAddress((void**)&kh, g_kh);   cudaGetSymbolAddress((void**)&km, g_km);   cudaGetSymbolAddress((void**)&kl, g_kl);
    cudaGetSymbolAddress((void**)&q2h, g_q2h); cudaGetSymbolAddress((void**)&q2m, g_q2m); cudaGetSymbolAddress((void**)&q2l, g_q2l);
    cudaGetSymbolAddress((void**)&vf,  g_vf);  cudaGetSymbolAddress((void**)&dv, g_dv);
    cudaGetSymbolAddress((void**)&e0h, g_e0h); cudaGetSymbolAddress((void**)&e0m, g_e0m); cudaGetSymbolAddress((void**)&e0l, g_e0l);
    cudaGetSymbolAddress((void**)&qh, g_qh);   cudaGetSymbolAddress((void**)&qm, g_qm);   cudaGetSymbolAddress((void**)&ql, g_ql);
    cudaGetSymbolAddress((void**)&cth, g_cth); cudaGetSymbolAddress((void**)&ctm, g_ctm); cudaGetSymbolAddress((void**)&ctl, g_ctl);
    cudaGetSymbolAddress((void**)&h1h, g_h1h); cudaGetSymbolAddress((void**)&h1m, g_h1m); cudaGetSymbolAddress((void**)&h1l, g_h1l);
    cudaGetSymbolAddress((void**)&eh, g_eh);   cudaGetSymbolAddress((void**)&em, g_em);   cudaGetSymbolAddress((void**)&el, g_el);
    cudaGetSymbolAddress((void**)&k2h, g_k2h); cudaGetSymbolAddress((void**)&k2m, g_k2m); cudaGetSymbolAddress((void**)&k2l, g_k2l);
    cudaGetSymbolAddress((void**)&wqh, g_WqTh); cudaGetSymbolAddress((void**)&wqm, g_WqTm); cudaGetSymbolAddress((void**)&wql, g_WqTl);
    cudaGetSymbolAddress((void**)&wkh, g_WkTh); cudaGetSymbolAddress((void**)&wkm, g_WkTm); cudaGetSymbolAddress((void**)&wkl, g_WkTl);
    cudaGetSymbolAddress((void**)&wvh, g_WvTh); cudaGetSymbolAddress((void**)&wvm, g_WvTm); cudaGetSymbolAddress((void**)&wvl, g_WvTl);
    cudaGetSymbolAddress((void**)&w1h, g_W1Th); cudaGetSymbolAddress((void**)&w1m, g_W1Tm); cudaGetSymbolAddress((void**)&w1l, g_W1Tl);
    cudaGetSymbolAddress((void**)&w2h, g_W2Th); cudaGetSymbolAddress((void**)&w2m, g_W2Tm); cudaGetSymbolAddress((void**)&w2l, g_W2Tl);

    const float scale = 1.0f / 32.0f;  // 1024^-0.5
    dim3 tb(32, 8);

    // weight transposes (T[N][K] = W[K][N])
    transpose_conv<<<dim3(DIM / 32, DIM / 32), tb>>>(Wq, wqh, wqm, wql, DIM, DIM);
    transpose_conv<<<dim3(DIM / 32, DIM / 32), tb>>>(Wk, wkh, wkm, wkl, DIM, DIM);
    transpose_conv<<<dim3(DIM / 32, DIM / 32), tb>>>(Wv, wvh, wvm, wvl, DIM, DIM);
    transpose_conv<<<dim3(HIDD / 32, (2 * DIM) / 32), tb>>>(W1, w1h, w1m, w1l, 2 * DIM, HIDD);
    transpose_conv<<<dim3(DIM / 32, HIDD / 32), tb>>>(W2, w2h, w2m, w2l, HIDD, DIM);

    // layernorms
    ln_kernel<<<N_NODES, 256>>>(inputs, gin, bin, xh, xm, xl);
    edge_ln_kernel<<<N_EDGE, 256>>>(noise, emu, elogsig, ge, be, e0h, e0m, e0l, cth, ctm, ctl);

    // k = relu(x@Wk+bk) -> triple
    big<<<dim3(DIM / 128, N_NODES / 64), 256, SMEM_BIG>>>(
        xh, xm, xl, wkh, wkm, wkl, bk, 1.f, 1, nullptr, kh, km, kl, N_NODES, DIM, DIM);
    // v = relu(x@Wv+bv) -> fp32
    big<<<dim3(DIM / 128, N_NODES / 64), 256, SMEM_BIG>>>(
        xh, xm, xl, wvh, wvm, wvl, bv, 1.f, 1, vf, nullptr, nullptr, nullptr, N_NODES, DIM, DIM);
    // q2 = x@Wq+bq (no relu) -> triple
    big<<<dim3(DIM / 128, N_NODES / 64), 256, SMEM_BIG>>>(
        xh, xm, xl, wqh, wqm, wql, bq, 1.f, 0, nullptr, q2h, q2m, q2l, N_NODES, DIM, DIM);
    // q = relu(e0@Wq+bq) -> triple
    small<<<dim3(DIM / 128, N_EDGE / 32), 256, SMEM_SMALL>>>(
        e0h, e0m, e0l, wqh, wqm, wql, bq, 1.f, 1, nullptr, qh, qm, ql, N_EDGE, DIM, DIM);
    // dots = scale * q@k^T -> fp32 (output)
    big<<<dim3(N_NODES / 128, N_EDGE / 64), 256, SMEM_BIG>>>(
        qh, qm, ql, kh, km, kl, nullptr, scale, 0, out_dots, nullptr, nullptr, nullptr, N_EDGE, N_NODES, DIM);
    // sparse top-k attention -> cat second half (triple)
    attn_update_kernel<<<N_EDGE, 256>>>(out_dots, vf, kn, cth, ctm, ctl);
    // h1 = relu(cat@W1+b1) -> triple
    small<<<dim3(HIDD / 128, N_EDGE / 32), 256, SMEM_SMALL>>>(
        cth, ctm, ctl, w1h, w1m, w1l, b1, 1.f, 1, nullptr, h1h, h1m, h1l, N_EDGE, HIDD, 2 * DIM);
    // edges = h1@W2+b2 -> fp32 output + triple
    small<<<dim3(DIM / 128, N_EDGE / 32), 256, SMEM_SMALL>>>(
        h1h, h1m, h1l, w2h, w2m, w2l, b2, 1.f, 0, out_edges, eh, em, el, N_EDGE, DIM, HIDD);
    // k2 = relu(edges@Wk+bk) -> triple
    small<<<dim3(DIM / 128, N_EDGE / 32), 256, SMEM_SMALL>>>(
        eh, em, el, wkh, wkm, wkl, bk, 1.f, 1, nullptr, k2h, k2m, k2l, N_EDGE, DIM, DIM);
    // dots_v = scale * q2@k2^T -> fp32
    big<<<dim3(N_EDGE / 128, N_NODES / 64), 256, SMEM_BIG>>>(
        q2h, q2m, q2l, k2h, k2m, k2l, nullptr, scale, 0, dv, nullptr, nullptr, nullptr, N_NODES, N_EDGE, DIM);
    // H
    h_kernel<<<N_NODES, 128>>>(dv, ke, out_H);
}